// round 1
// baseline (speedup 1.0000x reference)
#include <cuda_runtime.h>
#include <math.h>

// Problem constants
#define BB 4
#define TT 2048
#define CC 1024
#define HH 16
#define HS 64
#define MM (BB*TT)          // 8192 token rows

// Scratch (device globals: allocation-free rule)
__device__ float g_q[(size_t)MM*CC];
__device__ float g_k[(size_t)MM*CC];
__device__ float g_v[(size_t)MM*CC];
__device__ float g_y[(size_t)MM*CC];

// ---------------------------------------------------------------------------
// SGEMM: C[M,N] = A[M,K] @ B[K,N] + bias[N]
// 128x128 block tile, BK=8, 256 threads, 8x8 per-thread microtile.
// ---------------------------------------------------------------------------
__device__ __forceinline__ void sgemm128(const float* __restrict__ A,
                                         const float* __restrict__ B,
                                         const float* __restrict__ bias,
                                         float* __restrict__ C,
                                         int M, int N, int K)
{
    __shared__ float As[8][132];   // transposed A tile [k][m], padded
    __shared__ float Bs[8][128];   // B tile [k][n]

    const int tid = threadIdx.x;
    const int tx = tid & 15;
    const int ty = tid >> 4;
    const int row0 = blockIdx.y * 128;
    const int col0 = blockIdx.x * 128;

    float acc[8][8];
#pragma unroll
    for (int i = 0; i < 8; i++)
#pragma unroll
        for (int j = 0; j < 8; j++) acc[i][j] = 0.f;

    // global-load mapping (float4 per thread per tile)
    const int a_r = tid >> 1;            // 0..127
    const int a_c = (tid & 1) * 4;       // 0 or 4
    const int b_r = tid >> 5;            // 0..7
    const int b_c = (tid * 4) & 127;

    const float* Ap = A + (size_t)(row0 + a_r) * K + a_c;
    const float* Bp = B + (size_t)b_r * N + col0 + b_c;

    for (int k0 = 0; k0 < K; k0 += 8) {
        float4 av = *(const float4*)Ap;
        float4 bq = *(const float4*)Bp;
        As[a_c + 0][a_r] = av.x;
        As[a_c + 1][a_r] = av.y;
        As[a_c + 2][a_r] = av.z;
        As[a_c + 3][a_r] = av.w;
        *(float4*)&Bs[b_r][b_c] = bq;
        __syncthreads();

#pragma unroll
        for (int kk = 0; kk < 8; kk++) {
            float a[8], b[8];
            *(float4*)&a[0] = *(const float4*)&As[kk][ty * 8];
            *(float4*)&a[4] = *(const float4*)&As[kk][ty * 8 + 4];
            *(float4*)&b[0] = *(const float4*)&Bs[kk][tx * 8];
            *(float4*)&b[4] = *(const float4*)&Bs[kk][tx * 8 + 4];
#pragma unroll
            for (int i = 0; i < 8; i++)
#pragma unroll
                for (int j = 0; j < 8; j++)
                    acc[i][j] = fmaf(a[i], b[j], acc[i][j]);
        }
        __syncthreads();
        Ap += 8;
        Bp += (size_t)8 * N;
    }

#pragma unroll
    for (int i = 0; i < 8; i++) {
        int r = row0 + ty * 8 + i;
#pragma unroll
        for (int j = 0; j < 8; j += 4) {
            int c = col0 + tx * 8 + j;
            float4 o;
            o.x = acc[i][j + 0] + bias[c + 0];
            o.y = acc[i][j + 1] + bias[c + 1];
            o.z = acc[i][j + 2] + bias[c + 2];
            o.w = acc[i][j + 3] + bias[c + 3];
            *(float4*)&C[(size_t)r * N + c] = o;
        }
    }
}

// QKV projections: one launch, blockIdx.z selects {Q,K,V}.
__global__ __launch_bounds__(256, 2) void qkv_gemm_kernel(
    const float* __restrict__ x,
    const float* __restrict__ Wq, const float* __restrict__ bq,
    const float* __restrict__ Wk, const float* __restrict__ bk,
    const float* __restrict__ Wv, const float* __restrict__ bv)
{
    const float* W;
    const float* bias;
    float* O;
    if (blockIdx.z == 0)      { W = Wq; bias = bq; O = g_q; }
    else if (blockIdx.z == 1) { W = Wk; bias = bk; O = g_k; }
    else                      { W = Wv; bias = bv; O = g_v; }
    sgemm128(x, W, bias, O, MM, CC, CC);
}

// Output projection (reuses Wv/bv, matching the reference module)
__global__ __launch_bounds__(256, 2) void out_gemm_kernel(
    const float* __restrict__ Wv, const float* __restrict__ bv,
    float* __restrict__ out)
{
    sgemm128(g_y, Wv, bv, out, MM, CC, CC);
}

// ---------------------------------------------------------------------------
// Causal flash attention, fp32.
// Br=64 query rows per CTA, Bc=32 kv rows per inner block.
// grid = (T/64, B*H), 256 threads (16x16), online softmax.
// ---------------------------------------------------------------------------
__global__ __launch_bounds__(256, 1) void attn_kernel()
{
    __shared__ float Qt[64][68];   // [d][r]  (Q transposed, pre-scaled)
    __shared__ float Kt[64][36];   // [d][c]  (K transposed)
    __shared__ float Vs[32][68];   // [c][d]
    __shared__ float Pt[32][68];   // [c][r]  (P transposed)

    const int tid = threadIdx.x;
    const int tx = tid & 15;       // 16 -> 32 S-cols (x2), 64 O-cols (x4)
    const int ty = tid >> 4;       // 16 -> 64 rows (x4)
    const int qi = blockIdx.x;     // 0..31
    const int bh = blockIdx.y;     // 0..63
    const int b  = bh >> 4;
    const int h  = bh & 15;

    const float scale = 0.125f;    // 1/sqrt(64)
    const float NEG   = -1e30f;

    const float* Qg = g_q + (size_t)b * TT * CC + h * HS;
    const float* Kg = g_k + (size_t)b * TT * CC + h * HS;
    const float* Vg = g_v + (size_t)b * TT * CC + h * HS;

    // Load Q tile (64x64), store transposed, pre-scaled.
#pragma unroll
    for (int it = 0; it < 4; it++) {
        int idx = tid + it * 256;          // float4 index 0..1023
        int r  = idx >> 4;
        int d4 = (idx & 15) * 4;
        float4 v = *(const float4*)(Qg + (size_t)(qi * 64 + r) * CC + d4);
        Qt[d4 + 0][r] = v.x * scale;
        Qt[d4 + 1][r] = v.y * scale;
        Qt[d4 + 2][r] = v.z * scale;
        Qt[d4 + 3][r] = v.w * scale;
    }

    float m[4], l[4], acc[4][4];
#pragma unroll
    for (int i = 0; i < 4; i++) {
        m[i] = NEG;
        l[i] = 0.f;
#pragma unroll
        for (int j = 0; j < 4; j++) acc[i][j] = 0.f;
    }

    const int nkb = 2 * qi + 2;   // causal: kv blocks covering cols <= qi*64+63

    for (int jb = 0; jb < nkb; jb++) {
        __syncthreads();   // prev iter done with Kt/Vs/Pt (also covers Q load, iter 0)

        // Load K (transposed) and V tiles: 32 rows x 64 d each.
#pragma unroll
        for (int it = 0; it < 2; it++) {
            int idx = tid + it * 256;      // float4 index 0..511
            int c  = idx >> 4;
            int d4 = (idx & 15) * 4;
            const float* kp = Kg + (size_t)(jb * 32 + c) * CC + d4;
            float4 kv = *(const float4*)kp;
            Kt[d4 + 0][c] = kv.x;
            Kt[d4 + 1][c] = kv.y;
            Kt[d4 + 2][c] = kv.z;
            Kt[d4 + 3][c] = kv.w;
            const float* vp = Vg + (size_t)(jb * 32 + c) * CC + d4;
            *(float4*)&Vs[c][d4] = *(const float4*)vp;
        }
        __syncthreads();

        // S = (Q*scale) @ K^T : each thread 4 rows x 2 cols
        float s[4][2];
#pragma unroll
        for (int i = 0; i < 4; i++) { s[i][0] = 0.f; s[i][1] = 0.f; }
#pragma unroll 8
        for (int d = 0; d < 64; d++) {
            float4 a  = *(const float4*)&Qt[d][ty * 4];
            float2 kb = *(const float2*)&Kt[d][tx * 2];
            s[0][0] = fmaf(a.x, kb.x, s[0][0]);
            s[0][1] = fmaf(a.x, kb.y, s[0][1]);
            s[1][0] = fmaf(a.y, kb.x, s[1][0]);
            s[1][1] = fmaf(a.y, kb.y, s[1][1]);
            s[2][0] = fmaf(a.z, kb.x, s[2][0]);
            s[2][1] = fmaf(a.z, kb.y, s[2][1]);
            s[3][0] = fmaf(a.w, kb.x, s[3][0]);
            s[3][1] = fmaf(a.w, kb.y, s[3][1]);
        }

        // Causal mask (only the two diagonal-adjacent blocks need it)
        if (jb >= 2 * qi) {
#pragma unroll
            for (int i = 0; i < 4; i++) {
                int r = qi * 64 + ty * 4 + i;
#pragma unroll
                for (int j = 0; j < 2; j++) {
                    int c = jb * 32 + tx * 2 + j;
                    if (c > r) s[i][j] = NEG;
                }
            }
        }

        // Online softmax update
        float p[4][2];
#pragma unroll
        for (int i = 0; i < 4; i++) {
            float rm = fmaxf(s[i][0], s[i][1]);
#pragma unroll
            for (int off = 8; off >= 1; off >>= 1)
                rm = fmaxf(rm, __shfl_xor_sync(0xffffffffu, rm, off, 16));
            float mnew = fmaxf(m[i], rm);
            float f = __expf(m[i] - mnew);
            p[i][0] = __expf(s[i][0] - mnew);
            p[i][1] = __expf(s[i][1] - mnew);
            float rs = p[i][0] + p[i][1];
#pragma unroll
            for (int off = 8; off >= 1; off >>= 1)
                rs += __shfl_xor_sync(0xffffffffu, rs, off, 16);
            l[i] = l[i] * f + rs;
            m[i] = mnew;
#pragma unroll
            for (int j = 0; j < 4; j++) acc[i][j] *= f;
        }

        // Stage P transposed for the P@V GEMM
#pragma unroll
        for (int i = 0; i < 4; i++) {
            Pt[tx * 2 + 0][ty * 4 + i] = p[i][0];
            Pt[tx * 2 + 1][ty * 4 + i] = p[i][1];
        }
        __syncthreads();

        // O += P @ V : thread covers 4 rows x 4 d-cols
#pragma unroll 8
        for (int c = 0; c < 32; c++) {
            float4 pa = *(const float4*)&Pt[c][ty * 4];
            float4 vb = *(const float4*)&Vs[c][tx * 4];
            acc[0][0] = fmaf(pa.x, vb.x, acc[0][0]);
            acc[0][1] = fmaf(pa.x, vb.y, acc[0][1]);
            acc[0][2] = fmaf(pa.x, vb.z, acc[0][2]);
            acc[0][3] = fmaf(pa.x, vb.w, acc[0][3]);
            acc[1][0] = fmaf(pa.y, vb.x, acc[1][0]);
            acc[1][1] = fmaf(pa.y, vb.y, acc[1][1]);
            acc[1][2] = fmaf(pa.y, vb.z, acc[1][2]);
            acc[1][3] = fmaf(pa.y, vb.w, acc[1][3]);
            acc[2][0] = fmaf(pa.z, vb.x, acc[2][0]);
            acc[2][1] = fmaf(pa.z, vb.y, acc[2][1]);
            acc[2][2] = fmaf(pa.z, vb.z, acc[2][2]);
            acc[2][3] = fmaf(pa.z, vb.w, acc[2][3]);
            acc[3][0] = fmaf(pa.w, vb.x, acc[3][0]);
            acc[3][1] = fmaf(pa.w, vb.y, acc[3][1]);
            acc[3][2] = fmaf(pa.w, vb.z, acc[3][2]);
            acc[3][3] = fmaf(pa.w, vb.w, acc[3][3]);
        }
    }

    // Normalize and write y (pre-output-projection) back to [B,T,C] layout
#pragma unroll
    for (int i = 0; i < 4; i++) {
        float inv = 1.0f / l[i];
        int t = qi * 64 + ty * 4 + i;
        float4 o;
        o.x = acc[i][0] * inv;
        o.y = acc[i][1] * inv;
        o.z = acc[i][2] * inv;
        o.w = acc[i][3] * inv;
        *(float4*)(g_y + ((size_t)b * TT + t) * CC + h * HS + tx * 4) = o;
    }
}

// ---------------------------------------------------------------------------
extern "C" void kernel_launch(void* const* d_in, const int* in_sizes, int n_in,
                              void* d_out, int out_size)
{
    (void)in_sizes; (void)n_in; (void)out_size;
    const float* x  = (const float*)d_in[0];
    const float* Wq = (const float*)d_in[1];
    const float* bq = (const float*)d_in[2];
    const float* Wk = (const float*)d_in[3];
    const float* bk = (const float*)d_in[4];
    const float* Wv = (const float*)d_in[5];
    const float* bv = (const float*)d_in[6];
    float* out = (float*)d_out;

    dim3 gemm_grid(CC / 128, MM / 128);          // (8, 64)
    dim3 qkv_grid(CC / 128, MM / 128, 3);

    qkv_gemm_kernel<<<qkv_grid, 256>>>(x, Wq, bq, Wk, bk, Wv, bv);
    attn_kernel<<<dim3(TT / 64, BB * HH), 256>>>();
    out_gemm_kernel<<<gemm_grid, 256>>>(Wv, bv, out);
}

// round 3
// speedup vs baseline: 1.3417x; 1.3417x over previous
#include <cuda_runtime.h>
#include <cuda_bf16.h>
#include <cstdint>
#include <math.h>

// Problem constants
#define BB 4
#define TT 2048
#define CC 1024
#define HH 16
#define HS 64
#define MM (BB*TT)          // 8192 token rows

// Scratch (device globals: allocation-free rule)
__device__ float g_q[(size_t)MM*CC];
__device__ float g_k[(size_t)MM*CC];
__device__ float g_v[(size_t)MM*CC];
__device__ float g_y[(size_t)MM*CC];

// ---------------------------------------------------------------------------
// bf16 helpers
// ---------------------------------------------------------------------------
__device__ __forceinline__ uint32_t pk2(__nv_bfloat16 a, __nv_bfloat16 b) {
    return (uint32_t)__bfloat16_as_ushort(a) | ((uint32_t)__bfloat16_as_ushort(b) << 16);
}

__device__ __forceinline__ void split2(float x, float y, uint32_t& hi, uint32_t& lo) {
    __nv_bfloat16 hx = __float2bfloat16(x);
    __nv_bfloat16 hy = __float2bfloat16(y);
    __nv_bfloat16 lx = __float2bfloat16(x - __bfloat162float(hx));
    __nv_bfloat16 ly = __float2bfloat16(y - __bfloat162float(hy));
    hi = pk2(hx, hy);
    lo = pk2(lx, ly);
}

// m16n8k16 row.col bf16 MMA, f32 accumulate
__device__ __forceinline__ void mma16816(float* c, const uint32_t* a, const uint32_t* b) {
    asm volatile(
        "mma.sync.aligned.m16n8k16.row.col.f32.bf16.bf16.f32 "
        "{%0,%1,%2,%3}, {%4,%5,%6,%7}, {%8,%9}, {%0,%1,%2,%3};"
        : "+f"(c[0]), "+f"(c[1]), "+f"(c[2]), "+f"(c[3])
        : "r"(a[0]), "r"(a[1]), "r"(a[2]), "r"(a[3]), "r"(b[0]), "r"(b[1]));
}

// Swizzled smem fragment load: tile rows of 32 bf16 (16 b32 words),
// word w stored at w ^ (((row>>1)&3)<<2)  -> conflict-free LDS.32 frags.
__device__ __forceinline__ uint32_t lds_frag(const __nv_bfloat16* base, int r, int w) {
    int sw = ((r >> 1) & 3) << 2;
    return *(const uint32_t*)(base + r * 32 + ((w ^ sw) << 1));
}

// ---------------------------------------------------------------------------
// bf16x3 tensor GEMM: C[M,N] = A[M,K] @ W[K,N] + bias[N]
// 512 threads, CTA tile 128x128, BK=32, warp tile 32x32 (4x4 warp grid).
// ---------------------------------------------------------------------------
__device__ __forceinline__ void gemm_core(const float* __restrict__ A,
                                          const float* __restrict__ W,
                                          const float* __restrict__ bias,
                                          float* __restrict__ C)
{
    __shared__ __align__(16) __nv_bfloat16 AsH[128 * 32];
    __shared__ __align__(16) __nv_bfloat16 AsL[128 * 32];
    __shared__ __align__(16) __nv_bfloat16 BsH[128 * 32];
    __shared__ __align__(16) __nv_bfloat16 BsL[128 * 32];

    const int tid  = threadIdx.x;
    const int lane = tid & 31;
    const int wid  = tid >> 5;
    const int wm   = (wid & 3) * 32;    // warp M offset
    const int wn   = (wid >> 2) * 32;   // warp N offset
    const int lq   = lane >> 2;         // 0..7
    const int kq   = lane & 3;          // 0..3
    const int row0 = blockIdx.y * 128;
    const int col0 = blockIdx.x * 128;

    float acc[2][4][4];
#pragma unroll
    for (int mt = 0; mt < 2; mt++)
#pragma unroll
        for (int nt = 0; nt < 4; nt++)
#pragma unroll
            for (int i = 0; i < 4; i++) acc[mt][nt][i] = 0.f;

    // loader mapping
    const int a_r  = tid >> 3;          // 0..63 (and +64)
    const int a_f4 = tid & 7;           // float4 index in row
    const int b_n  = tid & 127;
    const int b_p0 = tid >> 7;          // pair group 0..3
    const float* Ag = A + (size_t)(row0 + a_r) * CC + a_f4 * 4;
    const float* Wg = W + (size_t)(2 * b_p0) * CC + col0 + b_n;

    // prefetch regs
    float4 pa0, pa1;
    float  pb[8];

    // preload chunk 0
    pa0 = *(const float4*)(Ag);
    pa1 = *(const float4*)(Ag + (size_t)64 * CC);
#pragma unroll
    for (int i = 0; i < 4; i++) {
        pb[2 * i]     = Wg[(size_t)(8 * i) * CC];
        pb[2 * i + 1] = Wg[(size_t)(8 * i + 1) * CC];
    }

#pragma unroll 1
    for (int ch = 0; ch < 32; ch++) {
        // ---- STS: convert prefetch regs -> hi/lo tiles ----
        {
            int r  = a_r;
            int w0 = a_f4 * 2;
            int sw = ((r >> 1) & 3) << 2;
            uint32_t h0, l0, h1, l1;
            split2(pa0.x, pa0.y, h0, l0);
            split2(pa0.z, pa0.w, h1, l1);
            *(uint2*)(AsH + r * 32 + ((w0 ^ sw) << 1)) = make_uint2(h0, h1);
            *(uint2*)(AsL + r * 32 + ((w0 ^ sw) << 1)) = make_uint2(l0, l1);
            r  = a_r + 64;
            sw = ((r >> 1) & 3) << 2;
            split2(pa1.x, pa1.y, h0, l0);
            split2(pa1.z, pa1.w, h1, l1);
            *(uint2*)(AsH + r * 32 + ((w0 ^ sw) << 1)) = make_uint2(h0, h1);
            *(uint2*)(AsL + r * 32 + ((w0 ^ sw) << 1)) = make_uint2(l0, l1);

            int swb = ((b_n >> 1) & 3) << 2;
#pragma unroll
            for (int i = 0; i < 4; i++) {
                int p = b_p0 + 4 * i;            // k-pair index 0..15
                uint32_t bh, bl;
                split2(pb[2 * i], pb[2 * i + 1], bh, bl);
                *(uint32_t*)(BsH + b_n * 32 + ((p ^ swb) << 1)) = bh;
                *(uint32_t*)(BsL + b_n * 32 + ((p ^ swb) << 1)) = bl;
            }
        }
        __syncthreads();

        // ---- prefetch next chunk ----
        if (ch < 31) {
            const int k0 = (ch + 1) * 32;
            pa0 = *(const float4*)(Ag + k0);
            pa1 = *(const float4*)(Ag + (size_t)64 * CC + k0);
#pragma unroll
            for (int i = 0; i < 4; i++) {
                pb[2 * i]     = Wg[(size_t)(k0 + 8 * i) * CC];
                pb[2 * i + 1] = Wg[(size_t)(k0 + 8 * i + 1) * CC];
            }
        }

        // ---- MMA phase: 2 k16 steps ----
#pragma unroll
        for (int ks = 0; ks < 2; ks++) {
            const int wb = ks * 8;
            uint32_t aH[2][4], aL[2][4], bH[4][2], bL[4][2];
#pragma unroll
            for (int mt = 0; mt < 2; mt++) {
                int r = wm + mt * 16 + lq;
                aH[mt][0] = lds_frag(AsH, r,     wb + kq);
                aH[mt][1] = lds_frag(AsH, r + 8, wb + kq);
                aH[mt][2] = lds_frag(AsH, r,     wb + kq + 4);
                aH[mt][3] = lds_frag(AsH, r + 8, wb + kq + 4);
                aL[mt][0] = lds_frag(AsL, r,     wb + kq);
                aL[mt][1] = lds_frag(AsL, r + 8, wb + kq);
                aL[mt][2] = lds_frag(AsL, r,     wb + kq + 4);
                aL[mt][3] = lds_frag(AsL, r + 8, wb + kq + 4);
            }
#pragma unroll
            for (int nt = 0; nt < 4; nt++) {
                int rn = wn + nt * 8 + lq;
                bH[nt][0] = lds_frag(BsH, rn, wb + kq);
                bH[nt][1] = lds_frag(BsH, rn, wb + kq + 4);
                bL[nt][0] = lds_frag(BsL, rn, wb + kq);
                bL[nt][1] = lds_frag(BsL, rn, wb + kq + 4);
            }
#pragma unroll
            for (int mt = 0; mt < 2; mt++)
#pragma unroll
                for (int nt = 0; nt < 4; nt++) {
                    mma16816(acc[mt][nt], aH[mt], bH[nt]);
                    mma16816(acc[mt][nt], aH[mt], bL[nt]);
                    mma16816(acc[mt][nt], aL[mt], bH[nt]);
                }
        }
        __syncthreads();
    }

    // ---- epilogue: bias add + STG ----
#pragma unroll
    for (int mt = 0; mt < 2; mt++) {
#pragma unroll
        for (int h2 = 0; h2 < 2; h2++) {
            int r = row0 + wm + mt * 16 + lq + h2 * 8;
            float* crow = C + (size_t)r * CC + col0 + wn;
#pragma unroll
            for (int nt = 0; nt < 4; nt++) {
                int cl = nt * 8 + kq * 2;
                float2 bv = *(const float2*)(bias + col0 + wn + cl);
                float2 o;
                o.x = acc[mt][nt][2 * h2 + 0] + bv.x;
                o.y = acc[mt][nt][2 * h2 + 1] + bv.y;
                *(float2*)(crow + cl) = o;
            }
        }
    }
}

// QKV projections: z selects {Q,K,V}
__global__ __launch_bounds__(512) void qkv_gemm_tc(
    const float* __restrict__ x,
    const float* __restrict__ Wq, const float* __restrict__ bq,
    const float* __restrict__ Wk, const float* __restrict__ bk,
    const float* __restrict__ Wv, const float* __restrict__ bv)
{
    const float* W; const float* bias; float* O;
    if (blockIdx.z == 0)      { W = Wq; bias = bq; O = g_q; }
    else if (blockIdx.z == 1) { W = Wk; bias = bk; O = g_k; }
    else                      { W = Wv; bias = bv; O = g_v; }
    gemm_core(x, W, bias, O);
}

// Output projection (reuses Wv/bv, matching the reference module)
__global__ __launch_bounds__(512) void out_gemm_tc(
    const float* __restrict__ Wv, const float* __restrict__ bv,
    float* __restrict__ out)
{
    gemm_core(g_y, Wv, bv, out);
}

// ---------------------------------------------------------------------------
// Causal flash attention, fp32 SIMT (round-1 version, unchanged).
// ---------------------------------------------------------------------------
__global__ __launch_bounds__(256, 1) void attn_kernel()
{
    __shared__ float Qt[64][68];
    __shared__ float Kt[64][36];
    __shared__ float Vs[32][68];
    __shared__ float Pt[32][68];

    const int tid = threadIdx.x;
    const int tx = tid & 15;
    const int ty = tid >> 4;
    const int qi = blockIdx.x;
    const int bh = blockIdx.y;
    const int b  = bh >> 4;
    const int h  = bh & 15;

    const float scale = 0.125f;
    const float NEG   = -1e30f;

    const float* Qg = g_q + (size_t)b * TT * CC + h * HS;
    const float* Kg = g_k + (size_t)b * TT * CC + h * HS;
    const float* Vg = g_v + (size_t)b * TT * CC + h * HS;

#pragma unroll
    for (int it = 0; it < 4; it++) {
        int idx = tid + it * 256;
        int r  = idx >> 4;
        int d4 = (idx & 15) * 4;
        float4 v = *(const float4*)(Qg + (size_t)(qi * 64 + r) * CC + d4);
        Qt[d4 + 0][r] = v.x * scale;
        Qt[d4 + 1][r] = v.y * scale;
        Qt[d4 + 2][r] = v.z * scale;
        Qt[d4 + 3][r] = v.w * scale;
    }

    float m[4], l[4], acc[4][4];
#pragma unroll
    for (int i = 0; i < 4; i++) {
        m[i] = NEG;
        l[i] = 0.f;
#pragma unroll
        for (int j = 0; j < 4; j++) acc[i][j] = 0.f;
    }

    const int nkb = 2 * qi + 2;

    for (int jb = 0; jb < nkb; jb++) {
        __syncthreads();

#pragma unroll
        for (int it = 0; it < 2; it++) {
            int idx = tid + it * 256;
            int c  = idx >> 4;
            int d4 = (idx & 15) * 4;
            const float* kp = Kg + (size_t)(jb * 32 + c) * CC + d4;
            float4 kv = *(const float4*)kp;
            Kt[d4 + 0][c] = kv.x;
            Kt[d4 + 1][c] = kv.y;
            Kt[d4 + 2][c] = kv.z;
            Kt[d4 + 3][c] = kv.w;
            const float* vp = Vg + (size_t)(jb * 32 + c) * CC + d4;
            *(float4*)&Vs[c][d4] = *(const float4*)vp;
        }
        __syncthreads();

        float s[4][2];
#pragma unroll
        for (int i = 0; i < 4; i++) { s[i][0] = 0.f; s[i][1] = 0.f; }
#pragma unroll 8
        for (int d = 0; d < 64; d++) {
            float4 a  = *(const float4*)&Qt[d][ty * 4];
            float2 kb = *(const float2*)&Kt[d][tx * 2];
            s[0][0] = fmaf(a.x, kb.x, s[0][0]);
            s[0][1] = fmaf(a.x, kb.y, s[0][1]);
            s[1][0] = fmaf(a.y, kb.x, s[1][0]);
            s[1][1] = fmaf(a.y, kb.y, s[1][1]);
            s[2][0] = fmaf(a.z, kb.x, s[2][0]);
            s[2][1] = fmaf(a.z, kb.y, s[2][1]);
            s[3][0] = fmaf(a.w, kb.x, s[3][0]);
            s[3][1] = fmaf(a.w, kb.y, s[3][1]);
        }

        if (jb >= 2 * qi) {
#pragma unroll
            for (int i = 0; i < 4; i++) {
                int r = qi * 64 + ty * 4 + i;
#pragma unroll
                for (int j = 0; j < 2; j++) {
                    int c = jb * 32 + tx * 2 + j;
                    if (c > r) s[i][j] = NEG;
                }
            }
        }

        float p[4][2];
#pragma unroll
        for (int i = 0; i < 4; i++) {
            float rm = fmaxf(s[i][0], s[i][1]);
#pragma unroll
            for (int off = 8; off >= 1; off >>= 1)
                rm = fmaxf(rm, __shfl_xor_sync(0xffffffffu, rm, off, 16));
            float mnew = fmaxf(m[i], rm);
            float f = __expf(m[i] - mnew);
            p[i][0] = __expf(s[i][0] - mnew);
            p[i][1] = __expf(s[i][1] - mnew);
            float rs = p[i][0] + p[i][1];
#pragma unroll
            for (int off = 8; off >= 1; off >>= 1)
                rs += __shfl_xor_sync(0xffffffffu, rs, off, 16);
            l[i] = l[i] * f + rs;
            m[i] = mnew;
#pragma unroll
            for (int j = 0; j < 4; j++) acc[i][j] *= f;
        }

#pragma unroll
        for (int i = 0; i < 4; i++) {
            Pt[tx * 2 + 0][ty * 4 + i] = p[i][0];
            Pt[tx * 2 + 1][ty * 4 + i] = p[i][1];
        }
        __syncthreads();

#pragma unroll 8
        for (int c = 0; c < 32; c++) {
            float4 pa = *(const float4*)&Pt[c][ty * 4];
            float4 vb = *(const float4*)&Vs[c][tx * 4];
            acc[0][0] = fmaf(pa.x, vb.x, acc[0][0]);
            acc[0][1] = fmaf(pa.x, vb.y, acc[0][1]);
            acc[0][2] = fmaf(pa.x, vb.z, acc[0][2]);
            acc[0][3] = fmaf(pa.x, vb.w, acc[0][3]);
            acc[1][0] = fmaf(pa.y, vb.x, acc[1][0]);
            acc[1][1] = fmaf(pa.y, vb.y, acc[1][1]);
            acc[1][2] = fmaf(pa.y, vb.z, acc[1][2]);
            acc[1][3] = fmaf(pa.y, vb.w, acc[1][3]);
            acc[2][0] = fmaf(pa.z, vb.x, acc[2][0]);
            acc[2][1] = fmaf(pa.z, vb.y, acc[2][1]);
            acc[2][2] = fmaf(pa.z, vb.z, acc[2][2]);
            acc[2][3] = fmaf(pa.z, vb.w, acc[2][3]);
            acc[3][0] = fmaf(pa.w, vb.x, acc[3][0]);
            acc[3][1] = fmaf(pa.w, vb.y, acc[3][1]);
            acc[3][2] = fmaf(pa.w, vb.z, acc[3][2]);
            acc[3][3] = fmaf(pa.w, vb.w, acc[3][3]);
        }
    }

#pragma unroll
    for (int i = 0; i < 4; i++) {
        float inv = 1.0f / l[i];
        int t = qi * 64 + ty * 4 + i;
        float4 o;
        o.x = acc[i][0] * inv;
        o.y = acc[i][1] * inv;
        o.z = acc[i][2] * inv;
        o.w = acc[i][3] * inv;
        *(float4*)(g_y + ((size_t)b * TT + t) * CC + h * HS + tx * 4) = o;
    }
}

// ---------------------------------------------------------------------------
extern "C" void kernel_launch(void* const* d_in, const int* in_sizes, int n_in,
                              void* d_out, int out_size)
{
    (void)in_sizes; (void)n_in; (void)out_size;
    const float* x  = (const float*)d_in[0];
    const float* Wq = (const float*)d_in[1];
    const float* bq = (const float*)d_in[2];
    const float* Wk = (const float*)d_in[3];
    const float* bk = (const float*)d_in[4];
    const float* Wv = (const float*)d_in[5];
    const float* bv = (const float*)d_in[6];
    float* out = (float*)d_out;

    dim3 qkv_grid(CC / 128, MM / 128, 3);        // (8, 64, 3)
    dim3 out_grid(CC / 128, MM / 128);           // (8, 64)

    qkv_gemm_tc<<<qkv_grid, 512>>>(x, Wq, bq, Wk, bk, Wv, bv);
    attn_kernel<<<dim3(TT / 64, BB * HH), 256>>>();
    out_gemm_tc<<<out_grid, 512>>>(Wv, bv, out);
}

// round 4
// speedup vs baseline: 1.8044x; 1.3449x over previous
#include <cuda_runtime.h>
#include <cuda_bf16.h>
#include <cstdint>
#include <math.h>

// Problem constants
#define BB 4
#define TT 2048
#define CC 1024
#define HH 16
#define HS 64
#define MM (BB*TT)          // 8192 token rows

// Scratch (device globals: allocation-free rule)
__device__ float g_q[(size_t)MM*CC];
__device__ float g_k[(size_t)MM*CC];
__device__ float g_v[(size_t)MM*CC];
__device__ float g_y[(size_t)MM*CC];

// ---------------------------------------------------------------------------
// bf16 helpers
// ---------------------------------------------------------------------------
__device__ __forceinline__ uint32_t pk2(__nv_bfloat16 a, __nv_bfloat16 b) {
    return (uint32_t)__bfloat16_as_ushort(a) | ((uint32_t)__bfloat16_as_ushort(b) << 16);
}

__device__ __forceinline__ void split2(float x, float y, uint32_t& hi, uint32_t& lo) {
    __nv_bfloat16 hx = __float2bfloat16(x);
    __nv_bfloat16 hy = __float2bfloat16(y);
    __nv_bfloat16 lx = __float2bfloat16(x - __bfloat162float(hx));
    __nv_bfloat16 ly = __float2bfloat16(y - __bfloat162float(hy));
    hi = pk2(hx, hy);
    lo = pk2(lx, ly);
}

// m16n8k16 row.col bf16 MMA, f32 accumulate
__device__ __forceinline__ void mma16816(float* c, const uint32_t* a, const uint32_t* b) {
    asm volatile(
        "mma.sync.aligned.m16n8k16.row.col.f32.bf16.bf16.f32 "
        "{%0,%1,%2,%3}, {%4,%5,%6,%7}, {%8,%9}, {%0,%1,%2,%3};"
        : "+f"(c[0]), "+f"(c[1]), "+f"(c[2]), "+f"(c[3])
        : "r"(a[0]), "r"(a[1]), "r"(a[2]), "r"(a[3]), "r"(b[0]), "r"(b[1]));
}

__device__ __forceinline__ void ldmx4(uint32_t* r, uint32_t addr) {
    asm volatile("ldmatrix.sync.aligned.m8n8.x4.shared.b16 {%0,%1,%2,%3}, [%4];"
                 : "=r"(r[0]), "=r"(r[1]), "=r"(r[2]), "=r"(r[3]) : "r"(addr));
}
__device__ __forceinline__ void ldmx4t(uint32_t* r, uint32_t addr) {
    asm volatile("ldmatrix.sync.aligned.m8n8.x4.trans.shared.b16 {%0,%1,%2,%3}, [%4];"
                 : "=r"(r[0]), "=r"(r[1]), "=r"(r[2]), "=r"(r[3]) : "r"(addr));
}

__device__ __forceinline__ uint32_t smem_u32(const void* p) {
    uint32_t a;
    asm("{ .reg .u64 t; cvta.to.shared.u64 t, %1; cvt.u32.u64 %0, t; }"
        : "=r"(a) : "l"(p));
    return a;
}

// ---------------------------------------------------------------------------
// GEMM smem swizzle (rows of 32 bf16 = 64B): word w at w ^ (((r>>1)&3)<<2)
// ---------------------------------------------------------------------------
__device__ __forceinline__ uint32_t lds_frag(const __nv_bfloat16* base, int r, int w) {
    int sw = ((r >> 1) & 3) << 2;
    return *(const uint32_t*)(base + r * 32 + ((w ^ sw) << 1));
}

// ---------------------------------------------------------------------------
// bf16x3 tensor GEMM, double-buffered: C[M,N] = A[M,K] @ W[K,N] + bias[N]
// 512 threads, CTA tile 128x128, BK=32, warp tile 32x32 (4x4 warp grid).
// Dynamic smem: 2 stages x {AsH,AsL,BsH,BsL} x 8KB = 64KB.
// ---------------------------------------------------------------------------
#define GEMM_SMEM 65536

__device__ __forceinline__ void gemm_sts(__nv_bfloat16* AsH, __nv_bfloat16* AsL,
                                         __nv_bfloat16* BsH, __nv_bfloat16* BsL,
                                         int a_r, int a_f4, int b_n, int b_p0,
                                         const float4& pa0, const float4& pa1,
                                         const float* pb)
{
    int r  = a_r;
    int w0 = a_f4 * 2;
    int sw = ((r >> 1) & 3) << 2;
    uint32_t h0, l0, h1, l1;
    split2(pa0.x, pa0.y, h0, l0);
    split2(pa0.z, pa0.w, h1, l1);
    *(uint2*)(AsH + r * 32 + ((w0 ^ sw) << 1)) = make_uint2(h0, h1);
    *(uint2*)(AsL + r * 32 + ((w0 ^ sw) << 1)) = make_uint2(l0, l1);
    r  = a_r + 64;
    sw = ((r >> 1) & 3) << 2;
    split2(pa1.x, pa1.y, h0, l0);
    split2(pa1.z, pa1.w, h1, l1);
    *(uint2*)(AsH + r * 32 + ((w0 ^ sw) << 1)) = make_uint2(h0, h1);
    *(uint2*)(AsL + r * 32 + ((w0 ^ sw) << 1)) = make_uint2(l0, l1);

    int swb = ((b_n >> 1) & 3) << 2;
#pragma unroll
    for (int i = 0; i < 4; i++) {
        int p = b_p0 + 4 * i;
        uint32_t bh, bl;
        split2(pb[2 * i], pb[2 * i + 1], bh, bl);
        *(uint32_t*)(BsH + b_n * 32 + ((p ^ swb) << 1)) = bh;
        *(uint32_t*)(BsL + b_n * 32 + ((p ^ swb) << 1)) = bl;
    }
}

__device__ __forceinline__ void gemm_core(const float* __restrict__ A,
                                          const float* __restrict__ W,
                                          const float* __restrict__ bias,
                                          float* __restrict__ C)
{
    extern __shared__ char smem_dyn[];
    __nv_bfloat16* AsH[2] = { (__nv_bfloat16*)(smem_dyn),
                              (__nv_bfloat16*)(smem_dyn + 32768) };
    __nv_bfloat16* AsL[2] = { (__nv_bfloat16*)(smem_dyn + 8192),
                              (__nv_bfloat16*)(smem_dyn + 40960) };
    __nv_bfloat16* BsH[2] = { (__nv_bfloat16*)(smem_dyn + 16384),
                              (__nv_bfloat16*)(smem_dyn + 49152) };
    __nv_bfloat16* BsL[2] = { (__nv_bfloat16*)(smem_dyn + 24576),
                              (__nv_bfloat16*)(smem_dyn + 57344) };

    const int tid  = threadIdx.x;
    const int lane = tid & 31;
    const int wid  = tid >> 5;
    const int wm   = (wid & 3) * 32;
    const int wn   = (wid >> 2) * 32;
    const int lq   = lane >> 2;
    const int kq   = lane & 3;
    const int row0 = blockIdx.y * 128;
    const int col0 = blockIdx.x * 128;

    float acc[2][4][4];
#pragma unroll
    for (int mt = 0; mt < 2; mt++)
#pragma unroll
        for (int nt = 0; nt < 4; nt++)
#pragma unroll
            for (int i = 0; i < 4; i++) acc[mt][nt][i] = 0.f;

    const int a_r  = tid >> 3;
    const int a_f4 = tid & 7;
    const int b_n  = tid & 127;
    const int b_p0 = tid >> 7;
    const float* Ag = A + (size_t)(row0 + a_r) * CC + a_f4 * 4;
    const float* Wg = W + (size_t)(2 * b_p0) * CC + col0 + b_n;

    float4 pa0, pa1;
    float  pb[8];

    // preload + stage chunk 0 into buffer 0
    pa0 = *(const float4*)(Ag);
    pa1 = *(const float4*)(Ag + (size_t)64 * CC);
#pragma unroll
    for (int i = 0; i < 4; i++) {
        pb[2 * i]     = Wg[(size_t)(8 * i) * CC];
        pb[2 * i + 1] = Wg[(size_t)(8 * i + 1) * CC];
    }
    gemm_sts(AsH[0], AsL[0], BsH[0], BsL[0], a_r, a_f4, b_n, b_p0, pa0, pa1, pb);
    __syncthreads();

#pragma unroll 1
    for (int ch = 0; ch < 32; ch++) {
        const int cur = ch & 1;

        // prefetch chunk ch+1
        if (ch < 31) {
            const int k0 = (ch + 1) * 32;
            pa0 = *(const float4*)(Ag + k0);
            pa1 = *(const float4*)(Ag + (size_t)64 * CC + k0);
#pragma unroll
            for (int i = 0; i < 4; i++) {
                pb[2 * i]     = Wg[(size_t)(k0 + 8 * i) * CC];
                pb[2 * i + 1] = Wg[(size_t)(k0 + 8 * i + 1) * CC];
            }
        }

        // MMA on current buffer
#pragma unroll
        for (int ks = 0; ks < 2; ks++) {
            const int wb = ks * 8;
            uint32_t aH[2][4], aL[2][4], bH[4][2], bL[4][2];
#pragma unroll
            for (int mt = 0; mt < 2; mt++) {
                int r = wm + mt * 16 + lq;
                aH[mt][0] = lds_frag(AsH[cur], r,     wb + kq);
                aH[mt][1] = lds_frag(AsH[cur], r + 8, wb + kq);
                aH[mt][2] = lds_frag(AsH[cur], r,     wb + kq + 4);
                aH[mt][3] = lds_frag(AsH[cur], r + 8, wb + kq + 4);
                aL[mt][0] = lds_frag(AsL[cur], r,     wb + kq);
                aL[mt][1] = lds_frag(AsL[cur], r + 8, wb + kq);
                aL[mt][2] = lds_frag(AsL[cur], r,     wb + kq + 4);
                aL[mt][3] = lds_frag(AsL[cur], r + 8, wb + kq + 4);
            }
#pragma unroll
            for (int nt = 0; nt < 4; nt++) {
                int rn = wn + nt * 8 + lq;
                bH[nt][0] = lds_frag(BsH[cur], rn, wb + kq);
                bH[nt][1] = lds_frag(BsH[cur], rn, wb + kq + 4);
                bL[nt][0] = lds_frag(BsL[cur], rn, wb + kq);
                bL[nt][1] = lds_frag(BsL[cur], rn, wb + kq + 4);
            }
#pragma unroll
            for (int mt = 0; mt < 2; mt++)
#pragma unroll
                for (int nt = 0; nt < 4; nt++) {
                    mma16816(acc[mt][nt], aH[mt], bH[nt]);
                    mma16816(acc[mt][nt], aH[mt], bL[nt]);
                    mma16816(acc[mt][nt], aL[mt], bH[nt]);
                }
        }

        // stage next chunk into other buffer
        if (ch < 31)
            gemm_sts(AsH[cur ^ 1], AsL[cur ^ 1], BsH[cur ^ 1], BsL[cur ^ 1],
                     a_r, a_f4, b_n, b_p0, pa0, pa1, pb);
        __syncthreads();
    }

    // ---- epilogue: bias add + STG ----
#pragma unroll
    for (int mt = 0; mt < 2; mt++) {
#pragma unroll
        for (int h2 = 0; h2 < 2; h2++) {
            int r = row0 + wm + mt * 16 + lq + h2 * 8;
            float* crow = C + (size_t)r * CC + col0 + wn;
#pragma unroll
            for (int nt = 0; nt < 4; nt++) {
                int cl = nt * 8 + kq * 2;
                float2 bv = *(const float2*)(bias + col0 + wn + cl);
                float2 o;
                o.x = acc[mt][nt][2 * h2 + 0] + bv.x;
                o.y = acc[mt][nt][2 * h2 + 1] + bv.y;
                *(float2*)(crow + cl) = o;
            }
        }
    }
}

__global__ __launch_bounds__(512) void qkv_gemm_tc(
    const float* __restrict__ x,
    const float* __restrict__ Wq, const float* __restrict__ bq,
    const float* __restrict__ Wk, const float* __restrict__ bk,
    const float* __restrict__ Wv, const float* __restrict__ bv)
{
    const float* W; const float* bias; float* O;
    if (blockIdx.z == 0)      { W = Wq; bias = bq; O = g_q; }
    else if (blockIdx.z == 1) { W = Wk; bias = bk; O = g_k; }
    else                      { W = Wv; bias = bv; O = g_v; }
    gemm_core(x, W, bias, O);
}

__global__ __launch_bounds__(512) void out_gemm_tc(
    const float* __restrict__ Wv, const float* __restrict__ bv,
    float* __restrict__ out)
{
    gemm_core(g_y, Wv, bv, out);
}

// ---------------------------------------------------------------------------
// Tensor-core causal flash attention (bf16x3).
// Br=128 (8 warps x m16), Bc=64, 256 threads, grid (T/128, B*H).
// Smem (64KB dyn): QsH/QsL [128][64], KsH/KsL [64][64], VsH/VsL [64][64] (t-major).
// Rows are 64 bf16 = 128B; word w of row r stored at w ^ ((r&7)<<2).
// ---------------------------------------------------------------------------
#define ATT_SMEM 65536

__device__ __forceinline__ uint32_t swa(uint32_t base, int r, int colbf) {
    int w0 = colbf >> 1;
    return base + (r << 7) + (((w0 ^ ((r & 7) << 2))) << 2);
}

__global__ __launch_bounds__(256) void attn_tc()
{
    extern __shared__ char smem_dyn[];
    const uint32_t sb  = smem_u32(smem_dyn);
    const uint32_t QsH = sb;
    const uint32_t QsL = sb + 16384;
    const uint32_t KsH = sb + 32768;
    const uint32_t KsL = sb + 40960;
    const uint32_t VsH = sb + 49152;
    const uint32_t VsL = sb + 57344;

    const int tid  = threadIdx.x;
    const int lane = tid & 31;
    const int wid  = tid >> 5;          // 0..7
    const int lq   = lane >> 2;
    const int kq   = lane & 3;
    const int qi   = (gridDim.x - 1) - blockIdx.x;   // big tiles first
    const int bh   = blockIdx.y;
    const int b    = bh >> 4;
    const int h    = bh & 15;
    const int wm   = wid * 16;          // warp's q-row offset in tile

    const float scale = 0.125f;

    const float* Qg = g_q + (size_t)b * TT * CC + h * HS;
    const float* Kg = g_k + (size_t)b * TT * CC + h * HS;
    const float* Vg = g_v + (size_t)b * TT * CC + h * HS;

    // ---- load Q tile (128 x 64), pre-scaled, hi/lo split ----
#pragma unroll
    for (int it = 0; it < 8; it++) {
        int idx = tid + it * 256;
        int r   = idx >> 4;
        int f4  = idx & 15;
        float4 v = *(const float4*)(Qg + (size_t)(qi * 128 + r) * CC + f4 * 4);
        uint32_t h0, l0, h1, l1;
        split2(v.x * scale, v.y * scale, h0, l0);
        split2(v.z * scale, v.w * scale, h1, l1);
        uint32_t ad = swa(QsH, r, f4 * 4);
        *(uint2*)(size_t)0;  // (placeholder removed below)
        // store via generic pointers:
        *(uint2*)(smem_dyn + (ad - sb))            = make_uint2(h0, h1);
        *(uint2*)(smem_dyn + (swa(QsL, r, f4 * 4) - sb)) = make_uint2(l0, l1);
    }

    // K/V prefetch regs (chunk jb=0)
    float4 kR[4], vR[4];
#pragma unroll
    for (int it = 0; it < 4; it++) {
        int idx = tid + it * 256;
        int r   = idx >> 4;
        int f4  = idx & 15;
        kR[it] = *(const float4*)(Kg + (size_t)r * CC + f4 * 4);
        vR[it] = *(const float4*)(Vg + (size_t)r * CC + f4 * 4);
    }

    // state
    float m0 = -1e30f, m1 = -1e30f, l0 = 0.f, l1 = 0.f;
    float o[8][4];
#pragma unroll
    for (int nt = 0; nt < 8; nt++)
#pragma unroll
        for (int i = 0; i < 4; i++) o[nt][i] = 0.f;

    const int nkb = 2 * qi + 2;

#pragma unroll 1
    for (int jb = 0; jb < nkb; jb++) {
        // ---- STS K/V from prefetch regs ----
#pragma unroll
        for (int it = 0; it < 4; it++) {
            int idx = tid + it * 256;
            int r   = idx >> 4;
            int f4  = idx & 15;
            uint32_t h0, lo0, h1, lo1;
            split2(kR[it].x, kR[it].y, h0, lo0);
            split2(kR[it].z, kR[it].w, h1, lo1);
            *(uint2*)(smem_dyn + (swa(KsH, r, f4 * 4) - sb)) = make_uint2(h0, h1);
            *(uint2*)(smem_dyn + (swa(KsL, r, f4 * 4) - sb)) = make_uint2(lo0, lo1);
            split2(vR[it].x, vR[it].y, h0, lo0);
            split2(vR[it].z, vR[it].w, h1, lo1);
            *(uint2*)(smem_dyn + (swa(VsH, r, f4 * 4) - sb)) = make_uint2(h0, h1);
            *(uint2*)(smem_dyn + (swa(VsL, r, f4 * 4) - sb)) = make_uint2(lo0, lo1);
        }
        __syncthreads();

        // ---- prefetch next K/V ----
        if (jb + 1 < nkb) {
            const size_t off = (size_t)(jb + 1) * 64 * CC;
#pragma unroll
            for (int it = 0; it < 4; it++) {
                int idx = tid + it * 256;
                int r   = idx >> 4;
                int f4  = idx & 15;
                kR[it] = *(const float4*)(Kg + off + (size_t)r * CC + f4 * 4);
                vR[it] = *(const float4*)(Vg + off + (size_t)r * CC + f4 * 4);
            }
        }

        // ---- S = Q @ K^T (bf16x3), S tile per warp: 16 x 64 ----
        float s[8][4];
#pragma unroll
        for (int nt = 0; nt < 8; nt++)
#pragma unroll
            for (int i = 0; i < 4; i++) s[nt][i] = 0.f;

        const int grp = lane >> 3;
        const int gi  = lane & 7;
#pragma unroll
        for (int ks = 0; ks < 4; ks++) {
            const int k0 = ks * 16;
            // A frags (Q): row = wm + gi + (grp&1)*8, col = k0 + (grp>>1)*8
            int ar = wm + gi + ((grp & 1) << 3);
            int ac = k0 + ((grp >> 1) << 3);
            uint32_t aH[4], aL[4];
            ldmx4(aH, swa(QsH, ar, ac));
            ldmx4(aL, swa(QsL, ar, ac));
#pragma unroll
            for (int ntp = 0; ntp < 4; ntp++) {
                // B frags (K, non-trans): n = ntp*16 + gi + (grp>>1)*8, k = k0 + (grp&1)*8
                int kn = ntp * 16 + gi + ((grp >> 1) << 3);
                int kk = k0 + ((grp & 1) << 3);
                uint32_t bH[4], bL[4];
                ldmx4(bH, swa(KsH, kn, kk));
                ldmx4(bL, swa(KsL, kn, kk));
                mma16816(s[2 * ntp],     aH, &bH[0]);
                mma16816(s[2 * ntp],     aH, &bL[0]);
                mma16816(s[2 * ntp],     aL, &bH[0]);
                mma16816(s[2 * ntp + 1], aH, &bH[2]);
                mma16816(s[2 * ntp + 1], aH, &bL[2]);
                mma16816(s[2 * ntp + 1], aL, &bH[2]);
            }
        }

        // ---- causal mask (only diagonal-adjacent blocks) ----
        if (jb >= 2 * qi) {
            int r0 = qi * 128 + wm + lq;
#pragma unroll
            for (int nt = 0; nt < 8; nt++) {
                int c = jb * 64 + nt * 8 + kq * 2;
                if (c > r0)     s[nt][0] = -1e30f;
                if (c + 1 > r0) s[nt][1] = -1e30f;
                if (c > r0 + 8)     s[nt][2] = -1e30f;
                if (c + 1 > r0 + 8) s[nt][3] = -1e30f;
            }
        }

        // ---- online softmax (rows lq, lq+8) ----
        float rm0 = -1e30f, rm1 = -1e30f;
#pragma unroll
        for (int nt = 0; nt < 8; nt++) {
            rm0 = fmaxf(rm0, fmaxf(s[nt][0], s[nt][1]));
            rm1 = fmaxf(rm1, fmaxf(s[nt][2], s[nt][3]));
        }
        rm0 = fmaxf(rm0, __shfl_xor_sync(0xffffffffu, rm0, 1));
        rm0 = fmaxf(rm0, __shfl_xor_sync(0xffffffffu, rm0, 2));
        rm1 = fmaxf(rm1, __shfl_xor_sync(0xffffffffu, rm1, 1));
        rm1 = fmaxf(rm1, __shfl_xor_sync(0xffffffffu, rm1, 2));

        float mn0 = fmaxf(m0, rm0);
        float mn1 = fmaxf(m1, rm1);
        float f0 = __expf(m0 - mn0);
        float f1 = __expf(m1 - mn1);
        m0 = mn0; m1 = mn1;

        float rs0 = 0.f, rs1 = 0.f;
#pragma unroll
        for (int nt = 0; nt < 8; nt++) {
            s[nt][0] = __expf(s[nt][0] - mn0);
            s[nt][1] = __expf(s[nt][1] - mn0);
            s[nt][2] = __expf(s[nt][2] - mn1);
            s[nt][3] = __expf(s[nt][3] - mn1);
            rs0 += s[nt][0] + s[nt][1];
            rs1 += s[nt][2] + s[nt][3];
        }
        rs0 += __shfl_xor_sync(0xffffffffu, rs0, 1);
        rs0 += __shfl_xor_sync(0xffffffffu, rs0, 2);
        rs1 += __shfl_xor_sync(0xffffffffu, rs1, 1);
        rs1 += __shfl_xor_sync(0xffffffffu, rs1, 2);
        l0 = l0 * f0 + rs0;
        l1 = l1 * f1 + rs1;

#pragma unroll
        for (int nt = 0; nt < 8; nt++) {
            o[nt][0] *= f0; o[nt][1] *= f0;
            o[nt][2] *= f1; o[nt][3] *= f1;
        }

        // ---- P fragments (A layout), hi/lo split, in-register ----
        uint32_t pH[4][4], pL[4][4];
#pragma unroll
        for (int ks = 0; ks < 4; ks++) {
            split2(s[2 * ks][0],     s[2 * ks][1],     pH[ks][0], pL[ks][0]);
            split2(s[2 * ks][2],     s[2 * ks][3],     pH[ks][1], pL[ks][1]);
            split2(s[2 * ks + 1][0], s[2 * ks + 1][1], pH[ks][2], pL[ks][2]);
            split2(s[2 * ks + 1][2], s[2 * ks + 1][3], pH[ks][3], pL[ks][3]);
        }

        // ---- O += P @ V ----
#pragma unroll
        for (int ks = 0; ks < 4; ks++) {
            const int k0 = ks * 16;
#pragma unroll
            for (int dtp = 0; dtp < 4; dtp++) {
                // B frags (V, trans): krow = k0 + gi + (grp&1)*8, dcol = dtp*16 + (grp>>1)*8
                int vr = k0 + gi + ((grp & 1) << 3);
                int vc = dtp * 16 + ((grp >> 1) << 3);
                uint32_t bH[4], bL[4];
                ldmx4t(bH, swa(VsH, vr, vc));
                ldmx4t(bL, swa(VsL, vr, vc));
                mma16816(o[2 * dtp],     pH[ks], &bH[0]);
                mma16816(o[2 * dtp],     pH[ks], &bL[0]);
                mma16816(o[2 * dtp],     pL[ks], &bH[0]);
                mma16816(o[2 * dtp + 1], pH[ks], &bH[2]);
                mma16816(o[2 * dtp + 1], pH[ks], &bL[2]);
                mma16816(o[2 * dtp + 1], pL[ks], &bH[2]);
            }
        }
        __syncthreads();
    }

    // ---- normalize + write y ----
    float inv0 = 1.0f / l0;
    float inv1 = 1.0f / l1;
    int r0 = qi * 128 + wm + lq;
    float* Y0 = g_y + ((size_t)b * TT + r0) * CC + h * HS;
    float* Y1 = g_y + ((size_t)b * TT + r0 + 8) * CC + h * HS;
#pragma unroll
    for (int nt = 0; nt < 8; nt++) {
        int c = nt * 8 + kq * 2;
        *(float2*)(Y0 + c) = make_float2(o[nt][0] * inv0, o[nt][1] * inv0);
        *(float2*)(Y1 + c) = make_float2(o[nt][2] * inv1, o[nt][3] * inv1);
    }
}

// ---------------------------------------------------------------------------
extern "C" void kernel_launch(void* const* d_in, const int* in_sizes, int n_in,
                              void* d_out, int out_size)
{
    (void)in_sizes; (void)n_in; (void)out_size;
    const float* x  = (const float*)d_in[0];
    const float* Wq = (const float*)d_in[1];
    const float* bq = (const float*)d_in[2];
    const float* Wk = (const float*)d_in[3];
    const float* bk = (const float*)d_in[4];
    const float* Wv = (const float*)d_in[5];
    const float* bv = (const float*)d_in[6];
    float* out = (float*)d_out;

    static bool configured = false;
    if (!configured) {
        cudaFuncSetAttribute(qkv_gemm_tc, cudaFuncAttributeMaxDynamicSharedMemorySize, GEMM_SMEM);
        cudaFuncSetAttribute(out_gemm_tc, cudaFuncAttributeMaxDynamicSharedMemorySize, GEMM_SMEM);
        cudaFuncSetAttribute(attn_tc,     cudaFuncAttributeMaxDynamicSharedMemorySize, ATT_SMEM);
        configured = true;
    }

    dim3 qkv_grid(CC / 128, MM / 128, 3);
    dim3 out_grid(CC / 128, MM / 128);

    qkv_gemm_tc<<<qkv_grid, 512, GEMM_SMEM>>>(x, Wq, bq, Wk, bk, Wv, bv);
    attn_tc<<<dim3(TT / 128, BB * HH), 256, ATT_SMEM>>>();
    out_gemm_tc<<<out_grid, 512, GEMM_SMEM>>>(Wv, bv, out);
}

// round 5
// speedup vs baseline: 3.1108x; 1.7240x over previous
#include <cuda_runtime.h>
#include <cuda_bf16.h>
#include <cstdint>
#include <math.h>

// Problem constants
#define BB 4
#define TT 2048
#define CC 1024
#define HH 16
#define HS 64
#define MM (BB*TT)          // 8192 token rows

// ---------------------------------------------------------------------------
// Device-global scratch (allocation-free rule). All bf16 hi/lo pairs.
// ---------------------------------------------------------------------------
__device__ __nv_bfloat16 g_xH[(size_t)MM*CC], g_xL[(size_t)MM*CC];
__device__ __nv_bfloat16 g_qH[(size_t)MM*CC], g_qL[(size_t)MM*CC];
__device__ __nv_bfloat16 g_kH[(size_t)MM*CC], g_kL[(size_t)MM*CC];
__device__ __nv_bfloat16 g_vH[(size_t)MM*CC], g_vL[(size_t)MM*CC];
__device__ __nv_bfloat16 g_yH[(size_t)MM*CC], g_yL[(size_t)MM*CC];
// W transposed to [n][k], 3 matrices (q,k,v)
__device__ __nv_bfloat16 g_wtH[(size_t)3*CC*CC], g_wtL[(size_t)3*CC*CC];

// ---------------------------------------------------------------------------
// helpers
// ---------------------------------------------------------------------------
__device__ __forceinline__ uint32_t pk2(__nv_bfloat16 a, __nv_bfloat16 b) {
    return (uint32_t)__bfloat16_as_ushort(a) | ((uint32_t)__bfloat16_as_ushort(b) << 16);
}
__device__ __forceinline__ void split1(float x, __nv_bfloat16& h, __nv_bfloat16& l) {
    h = __float2bfloat16(x);
    l = __float2bfloat16(x - __bfloat162float(h));
}
__device__ __forceinline__ void split2(float x, float y, uint32_t& hi, uint32_t& lo) {
    __nv_bfloat16 hx, lx, hy, ly;
    split1(x, hx, lx);
    split1(y, hy, ly);
    hi = pk2(hx, hy);
    lo = pk2(lx, ly);
}

__device__ __forceinline__ void mma16816(float* c, const uint32_t* a, const uint32_t* b) {
    asm volatile(
        "mma.sync.aligned.m16n8k16.row.col.f32.bf16.bf16.f32 "
        "{%0,%1,%2,%3}, {%4,%5,%6,%7}, {%8,%9}, {%0,%1,%2,%3};"
        : "+f"(c[0]), "+f"(c[1]), "+f"(c[2]), "+f"(c[3])
        : "r"(a[0]), "r"(a[1]), "r"(a[2]), "r"(a[3]), "r"(b[0]), "r"(b[1]));
}
__device__ __forceinline__ void ldmx4(uint32_t* r, uint32_t addr) {
    asm volatile("ldmatrix.sync.aligned.m8n8.x4.shared.b16 {%0,%1,%2,%3}, [%4];"
                 : "=r"(r[0]), "=r"(r[1]), "=r"(r[2]), "=r"(r[3]) : "r"(addr));
}
__device__ __forceinline__ void ldmx4t(uint32_t* r, uint32_t addr) {
    asm volatile("ldmatrix.sync.aligned.m8n8.x4.trans.shared.b16 {%0,%1,%2,%3}, [%4];"
                 : "=r"(r[0]), "=r"(r[1]), "=r"(r[2]), "=r"(r[3]) : "r"(addr));
}
__device__ __forceinline__ uint32_t smem_u32(const void* p) {
    uint32_t a;
    asm("{ .reg .u64 t; cvta.to.shared.u64 t, %1; cvt.u32.u64 %0, t; }"
        : "=r"(a) : "l"(p));
    return a;
}
__device__ __forceinline__ void cpa16(uint32_t s, const void* g) {
    asm volatile("cp.async.cg.shared.global [%0], [%1], 16;" :: "r"(s), "l"(g));
}
#define CP_COMMIT() asm volatile("cp.async.commit_group;")
#define CP_WAIT0()  asm volatile("cp.async.wait_group 0;")

// ---------------------------------------------------------------------------
// Pre-pass: split x into hi/lo bf16
// ---------------------------------------------------------------------------
__global__ __launch_bounds__(256) void split_x_kernel(const float* __restrict__ x)
{
    size_t i = (size_t)blockIdx.x * 256 + threadIdx.x;   // float4 index
    float4 v = ((const float4*)x)[i];
    uint32_t h0, l0, h1, l1;
    split2(v.x, v.y, h0, l0);
    split2(v.z, v.w, h1, l1);
    ((uint2*)g_xH)[i] = make_uint2(h0, h1);
    ((uint2*)g_xL)[i] = make_uint2(l0, l1);
}

// Pre-pass: transpose W [k][n] -> [n][k] and split hi/lo. grid (32,32,3), block (32,32)
__global__ __launch_bounds__(1024) void split_w_kernel(
    const float* __restrict__ Wq, const float* __restrict__ Wk, const float* __restrict__ Wv)
{
    __shared__ float tile[32][33];
    const float* W = blockIdx.z == 0 ? Wq : (blockIdx.z == 1 ? Wk : Wv);
    int n0 = blockIdx.x * 32, k0 = blockIdx.y * 32;
    tile[threadIdx.y][threadIdx.x] = W[(size_t)(k0 + threadIdx.y) * CC + n0 + threadIdx.x];
    __syncthreads();
    float v = tile[threadIdx.x][threadIdx.y];            // W[k0+tx][n0+ty]
    __nv_bfloat16 h, l;
    split1(v, h, l);
    size_t o = (size_t)blockIdx.z * CC * CC + (size_t)(n0 + threadIdx.y) * CC + k0 + threadIdx.x;
    g_wtH[o] = h;
    g_wtL[o] = l;
}

// ---------------------------------------------------------------------------
// bf16x3 GEMM v3: C = A @ Wt^T + bias   (A [M][K] hi/lo, Wt [N][K] hi/lo)
// 512 threads, CTA 128x128, BK=64, cp.async double buffer, ldmatrix frags.
// smem stage (64KB): AH 16K | AL 16K | BH 16K | BL 16K. 2 stages = 128KB.
// Swizzle: row of 64 bf16 = 128B = 8 x 16B units; unit u of row r at u^(r&7).
// ---------------------------------------------------------------------------
#define GEMM_SMEM 131072

template<int OUT_BF16>
__device__ __forceinline__ void gemm3_core(
    const __nv_bfloat16* __restrict__ AH, const __nv_bfloat16* __restrict__ AL,
    const __nv_bfloat16* __restrict__ BtH, const __nv_bfloat16* __restrict__ BtL,
    const float* __restrict__ bias, float scale,
    float* __restrict__ Cf, __nv_bfloat16* __restrict__ CoH, __nv_bfloat16* __restrict__ CoL)
{
    extern __shared__ char sm[];
    const uint32_t sbase = smem_u32(sm);

    const int tid  = threadIdx.x;
    const int lane = tid & 31;
    const int wid  = tid >> 5;
    const int wm   = (wid & 3) * 32;
    const int wn   = (wid >> 2) * 32;
    const int lq   = lane >> 2;
    const int kq   = lane & 3;
    const int gi   = lane & 7;
    const int grp  = lane >> 3;
    const int row0 = blockIdx.y * 128;
    const int col0 = blockIdx.x * 128;

    float acc[2][4][4];
#pragma unroll
    for (int mt = 0; mt < 2; mt++)
#pragma unroll
        for (int nt = 0; nt < 4; nt++)
#pragma unroll
            for (int i = 0; i < 4; i++) acc[mt][nt][i] = 0.f;

    // cp.async mapping: r = tid>>2 (0..127), units (tid&3)*2 + {0,1}
    const int cr  = tid >> 2;
    const int cu0 = (tid & 3) << 1;
    const __nv_bfloat16* gAH = AH + (size_t)(row0 + cr) * CC;
    const __nv_bfloat16* gAL = AL + (size_t)(row0 + cr) * CC;
    const __nv_bfloat16* gBH = BtH + (size_t)(col0 + cr) * CC;
    const __nv_bfloat16* gBL = BtL + (size_t)(col0 + cr) * CC;
    const uint32_t crow = cr * 128;

    auto issue = [&](int k0, int stg) {
        uint32_t sb = sbase + stg * 65536 + crow;
#pragma unroll
        for (int j = 0; j < 2; j++) {
            int u = cu0 + j;
            uint32_t d = sb + ((u ^ (cr & 7)) << 4);
            cpa16(d,         gAH + k0 + u * 8);
            cpa16(d + 16384, gAL + k0 + u * 8);
            cpa16(d + 32768, gBH + k0 + u * 8);
            cpa16(d + 49152, gBL + k0 + u * 8);
        }
    };

    // frag address components
    const uint32_t aRow = (wm + (lane & 15)) * 128;   // + mt*2048
    const int aSel = lane >> 4;                        // unit low bit
    const uint32_t bRow = (wn + gi + ((grp >> 1) << 3)) * 128;  // + ng*2048
    const int bSel = grp & 1;

    issue(0, 0);
    CP_COMMIT();

#pragma unroll 1
    for (int ch = 0; ch < 16; ch++) {
        const int stg = ch & 1;
        CP_WAIT0();
        __syncthreads();
        if (ch < 15) {
            issue((ch + 1) * 64, stg ^ 1);
            CP_COMMIT();
        }

        const uint32_t As = sbase + stg * 65536;
        const uint32_t Bs = As + 32768;
#pragma unroll
        for (int ks = 0; ks < 4; ks++) {
            uint32_t aH[2][4], aL[2][4], bH[2][4], bL[2][4];
#pragma unroll
            for (int mt = 0; mt < 2; mt++) {
                uint32_t ad = As + aRow + mt * 2048 +
                              ((((ks << 1) + aSel) ^ gi) << 4);
                ldmx4(aH[mt], ad);
                ldmx4(aL[mt], ad + 16384);
            }
#pragma unroll
            for (int ng = 0; ng < 2; ng++) {
                uint32_t bd = Bs + bRow + ng * 2048 +
                              ((((ks << 1) + bSel) ^ gi) << 4);
                ldmx4(bH[ng], bd);
                ldmx4(bL[ng], bd + 16384);
            }
#pragma unroll
            for (int mt = 0; mt < 2; mt++)
#pragma unroll
                for (int ng = 0; ng < 2; ng++) {
                    mma16816(acc[mt][2 * ng],     aH[mt], &bH[ng][0]);
                    mma16816(acc[mt][2 * ng],     aH[mt], &bL[ng][0]);
                    mma16816(acc[mt][2 * ng],     aL[mt], &bH[ng][0]);
                    mma16816(acc[mt][2 * ng + 1], aH[mt], &bH[ng][2]);
                    mma16816(acc[mt][2 * ng + 1], aH[mt], &bL[ng][2]);
                    mma16816(acc[mt][2 * ng + 1], aL[mt], &bH[ng][2]);
                }
        }
        __syncthreads();
    }

    // ---- epilogue ----
#pragma unroll
    for (int mt = 0; mt < 2; mt++) {
#pragma unroll
        for (int h2 = 0; h2 < 2; h2++) {
            int r = row0 + wm + mt * 16 + lq + h2 * 8;
#pragma unroll
            for (int nt = 0; nt < 4; nt++) {
                int c = col0 + wn + nt * 8 + kq * 2;
                float2 bv = *(const float2*)(bias + c);
                float v0 = (acc[mt][nt][2 * h2 + 0] + bv.x) * scale;
                float v1 = (acc[mt][nt][2 * h2 + 1] + bv.y) * scale;
                if (OUT_BF16) {
                    uint32_t hi, lo;
                    split2(v0, v1, hi, lo);
                    size_t idx = (size_t)r * CC + c;
                    *(uint32_t*)(CoH + idx) = hi;
                    *(uint32_t*)(CoL + idx) = lo;
                } else {
                    *(float2*)(Cf + (size_t)r * CC + c) = make_float2(v0, v1);
                }
            }
        }
    }
}

// QKV: z selects matrix; writes bf16 hi/lo (q pre-scaled by 1/8)
__global__ __launch_bounds__(512) void qkv_gemm_tc(
    const float* __restrict__ bq, const float* __restrict__ bk, const float* __restrict__ bv)
{
    const float* bias;
    __nv_bfloat16 *oH, *oL;
    float scale = 1.0f;
    if (blockIdx.z == 0)      { bias = bq; oH = g_qH; oL = g_qL; scale = 0.125f; }
    else if (blockIdx.z == 1) { bias = bk; oH = g_kH; oL = g_kL; }
    else                      { bias = bv; oH = g_vH; oL = g_vL; }
    const size_t wo = (size_t)blockIdx.z * CC * CC;
    gemm3_core<1>(g_xH, g_xL, g_wtH + wo, g_wtL + wo, bias, scale,
                  nullptr, oH, oL);
}

// Output projection: A = y (hi/lo), B = Wv (slot 2), fp32 out
__global__ __launch_bounds__(512) void out_gemm_tc(
    const float* __restrict__ bv, float* __restrict__ out)
{
    const size_t wo = (size_t)2 * CC * CC;
    gemm3_core<0>(g_yH, g_yL, g_wtH + wo, g_wtL + wo, bv, 1.0f,
                  out, nullptr, nullptr);
}

// ---------------------------------------------------------------------------
// Tensor-core causal flash attention v2 (bf16x3, cp.async, all-bf16 I/O).
// Br=128 (8 warps x m16), Bc=64, 256 threads, grid (T/128, B*H).
// smem: QH 16K | QL 16K | stage s: {KH 8K | KL 8K | VH 8K | VL 8K} x2 = 96KB
// ---------------------------------------------------------------------------
#define ATT_SMEM 98304

__global__ __launch_bounds__(256) void attn_tc()
{
    extern __shared__ char sm[];
    const uint32_t sbase = smem_u32(sm);
    const uint32_t QH = sbase, QL = sbase + 16384;

    const int tid  = threadIdx.x;
    const int lane = tid & 31;
    const int wid  = tid >> 5;
    const int lq   = lane >> 2;
    const int kq   = lane & 3;
    const int gi   = lane & 7;
    const int grp  = lane >> 3;
    const int qi   = (gridDim.x - 1) - blockIdx.x;
    const int bh   = blockIdx.y;
    const int b    = bh >> 4;
    const int h    = bh & 15;
    const int wm   = wid * 16;

    const size_t base = (size_t)b * TT * CC + h * HS;

    // ---- Q cp.async: r = tid>>1 (0..127), units (tid&1)*4 + 0..3 ----
    {
        int r  = tid >> 1;
        int u0 = (tid & 1) * 4;
        const __nv_bfloat16* gq = g_qH + base + (size_t)(qi * 128 + r) * CC;
        const __nv_bfloat16* gl = g_qL + base + (size_t)(qi * 128 + r) * CC;
        uint32_t d = QH + r * 128;
#pragma unroll
        for (int j = 0; j < 4; j++) {
            int u = u0 + j;
            uint32_t sw = ((u ^ (r & 7)) << 4);
            cpa16(d + sw,         gq + u * 8);
            cpa16(d + sw + 16384, gl + u * 8);
        }
    }

    // ---- K/V cp.async: r = tid>>2 (0..63), units (tid&3)*2 + {0,1} ----
    const int cr  = tid >> 2;
    const int cu0 = (tid & 3) << 1;
    const __nv_bfloat16* gKH = g_kH + base + (size_t)cr * CC;
    const __nv_bfloat16* gKL = g_kL + base + (size_t)cr * CC;
    const __nv_bfloat16* gVH = g_vH + base + (size_t)cr * CC;
    const __nv_bfloat16* gVL = g_vL + base + (size_t)cr * CC;

    auto issue_kv = [&](int jb, int stg) {
        uint32_t sb = sbase + 32768 + stg * 32768 + cr * 128;
        size_t off = (size_t)jb * 64 * CC;
#pragma unroll
        for (int j = 0; j < 2; j++) {
            int u = cu0 + j;
            uint32_t d = sb + ((u ^ (cr & 7)) << 4);
            cpa16(d,         gKH + off + u * 8);
            cpa16(d + 8192,  gKL + off + u * 8);
            cpa16(d + 16384, gVH + off + u * 8);
            cpa16(d + 24576, gVL + off + u * 8);
        }
    };

    issue_kv(0, 0);
    CP_COMMIT();

    float m0 = -1e30f, m1 = -1e30f, l0 = 0.f, l1 = 0.f;
    float o[8][4];
#pragma unroll
    for (int nt = 0; nt < 8; nt++)
#pragma unroll
        for (int i = 0; i < 4; i++) o[nt][i] = 0.f;

    const int nkb = 2 * qi + 2;

#pragma unroll 1
    for (int jb = 0; jb < nkb; jb++) {
        const int stg = jb & 1;
        CP_WAIT0();
        __syncthreads();
        if (jb + 1 < nkb) {
            issue_kv(jb + 1, stg ^ 1);
            CP_COMMIT();
        }

        const uint32_t Ks = sbase + 32768 + stg * 32768;
        const uint32_t Vs = Ks + 16384;

        // ---- S = Q @ K^T ----
        float s[8][4];
#pragma unroll
        for (int nt = 0; nt < 8; nt++)
#pragma unroll
            for (int i = 0; i < 4; i++) s[nt][i] = 0.f;

#pragma unroll
        for (int ks = 0; ks < 4; ks++) {
            uint32_t ad = QH + (wm + (lane & 15)) * 128 +
                          ((((ks << 1) + (lane >> 4)) ^ gi) << 4);
            uint32_t aH[4], aL[4];
            ldmx4(aH, ad);
            ldmx4(aL, ad + 16384);
#pragma unroll
            for (int ntp = 0; ntp < 4; ntp++) {
                uint32_t bd = Ks + (ntp * 16 + gi + ((grp >> 1) << 3)) * 128 +
                              ((((ks << 1) + (grp & 1)) ^ gi) << 4);
                uint32_t bH[4], bL[4];
                ldmx4(bH, bd);
                ldmx4(bL, bd + 8192);
                mma16816(s[2 * ntp],     aH, &bH[0]);
                mma16816(s[2 * ntp],     aH, &bL[0]);
                mma16816(s[2 * ntp],     aL, &bH[0]);
                mma16816(s[2 * ntp + 1], aH, &bH[2]);
                mma16816(s[2 * ntp + 1], aH, &bL[2]);
                mma16816(s[2 * ntp + 1], aL, &bH[2]);
            }
        }

        // ---- causal mask ----
        if (jb >= 2 * qi) {
            int r0 = qi * 128 + wm + lq;
#pragma unroll
            for (int nt = 0; nt < 8; nt++) {
                int c = jb * 64 + nt * 8 + kq * 2;
                if (c > r0)         s[nt][0] = -1e30f;
                if (c + 1 > r0)     s[nt][1] = -1e30f;
                if (c > r0 + 8)     s[nt][2] = -1e30f;
                if (c + 1 > r0 + 8) s[nt][3] = -1e30f;
            }
        }

        // ---- online softmax ----
        float rm0 = -1e30f, rm1 = -1e30f;
#pragma unroll
        for (int nt = 0; nt < 8; nt++) {
            rm0 = fmaxf(rm0, fmaxf(s[nt][0], s[nt][1]));
            rm1 = fmaxf(rm1, fmaxf(s[nt][2], s[nt][3]));
        }
        rm0 = fmaxf(rm0, __shfl_xor_sync(0xffffffffu, rm0, 1));
        rm0 = fmaxf(rm0, __shfl_xor_sync(0xffffffffu, rm0, 2));
        rm1 = fmaxf(rm1, __shfl_xor_sync(0xffffffffu, rm1, 1));
        rm1 = fmaxf(rm1, __shfl_xor_sync(0xffffffffu, rm1, 2));

        float mn0 = fmaxf(m0, rm0);
        float mn1 = fmaxf(m1, rm1);
        float f0 = __expf(m0 - mn0);
        float f1 = __expf(m1 - mn1);
        m0 = mn0; m1 = mn1;

        float rs0 = 0.f, rs1 = 0.f;
#pragma unroll
        for (int nt = 0; nt < 8; nt++) {
            s[nt][0] = __expf(s[nt][0] - mn0);
            s[nt][1] = __expf(s[nt][1] - mn0);
            s[nt][2] = __expf(s[nt][2] - mn1);
            s[nt][3] = __expf(s[nt][3] - mn1);
            rs0 += s[nt][0] + s[nt][1];
            rs1 += s[nt][2] + s[nt][3];
        }
        rs0 += __shfl_xor_sync(0xffffffffu, rs0, 1);
        rs0 += __shfl_xor_sync(0xffffffffu, rs0, 2);
        rs1 += __shfl_xor_sync(0xffffffffu, rs1, 1);
        rs1 += __shfl_xor_sync(0xffffffffu, rs1, 2);
        l0 = l0 * f0 + rs0;
        l1 = l1 * f1 + rs1;

#pragma unroll
        for (int nt = 0; nt < 8; nt++) {
            o[nt][0] *= f0; o[nt][1] *= f0;
            o[nt][2] *= f1; o[nt][3] *= f1;
        }

        // ---- P frags (A layout), hi/lo in-register ----
        uint32_t pH[4][4], pL[4][4];
#pragma unroll
        for (int ks = 0; ks < 4; ks++) {
            split2(s[2 * ks][0],     s[2 * ks][1],     pH[ks][0], pL[ks][0]);
            split2(s[2 * ks][2],     s[2 * ks][3],     pH[ks][1], pL[ks][1]);
            split2(s[2 * ks + 1][0], s[2 * ks + 1][1], pH[ks][2], pL[ks][2]);
            split2(s[2 * ks + 1][2], s[2 * ks + 1][3], pH[ks][3], pL[ks][3]);
        }

        // ---- O += P @ V ----
#pragma unroll
        for (int ks = 0; ks < 4; ks++) {
#pragma unroll
            for (int dtp = 0; dtp < 4; dtp++) {
                int vr = ks * 16 + gi + ((grp & 1) << 3);
                uint32_t vd = Vs + vr * 128 +
                              ((((dtp << 1) + (grp >> 1)) ^ gi) << 4);
                uint32_t bH[4], bL[4];
                ldmx4t(bH, vd);
                ldmx4t(bL, vd + 8192);
                mma16816(o[2 * dtp],     pH[ks], &bH[0]);
                mma16816(o[2 * dtp],     pH[ks], &bL[0]);
                mma16816(o[2 * dtp],     pL[ks], &bH[0]);
                mma16816(o[2 * dtp + 1], pH[ks], &bH[2]);
                mma16816(o[2 * dtp + 1], pH[ks], &bL[2]);
                mma16816(o[2 * dtp + 1], pL[ks], &bH[2]);
            }
        }
        __syncthreads();
    }

    // ---- normalize + write y as hi/lo bf16 ----
    float inv0 = 1.0f / l0;
    float inv1 = 1.0f / l1;
    int r0 = qi * 128 + wm + lq;
    size_t i0 = (size_t)b * TT * CC + (size_t)r0 * CC + h * HS;
    size_t i1 = i0 + 8 * CC;
#pragma unroll
    for (int nt = 0; nt < 8; nt++) {
        int c = nt * 8 + kq * 2;
        uint32_t hi, lo;
        split2(o[nt][0] * inv0, o[nt][1] * inv0, hi, lo);
        *(uint32_t*)(g_yH + i0 + c) = hi;
        *(uint32_t*)(g_yL + i0 + c) = lo;
        split2(o[nt][2] * inv1, o[nt][3] * inv1, hi, lo);
        *(uint32_t*)(g_yH + i1 + c) = hi;
        *(uint32_t*)(g_yL + i1 + c) = lo;
    }
}

// ---------------------------------------------------------------------------
extern "C" void kernel_launch(void* const* d_in, const int* in_sizes, int n_in,
                              void* d_out, int out_size)
{
    (void)in_sizes; (void)n_in; (void)out_size;
    const float* x  = (const float*)d_in[0];
    const float* Wq = (const float*)d_in[1];
    const float* bq = (const float*)d_in[2];
    const float* Wk = (const float*)d_in[3];
    const float* bk = (const float*)d_in[4];
    const float* Wv = (const float*)d_in[5];
    const float* bv = (const float*)d_in[6];
    float* out = (float*)d_out;

    static bool configured = false;
    if (!configured) {
        cudaFuncSetAttribute(qkv_gemm_tc, cudaFuncAttributeMaxDynamicSharedMemorySize, GEMM_SMEM);
        cudaFuncSetAttribute(out_gemm_tc, cudaFuncAttributeMaxDynamicSharedMemorySize, GEMM_SMEM);
        cudaFuncSetAttribute(attn_tc,     cudaFuncAttributeMaxDynamicSharedMemorySize, ATT_SMEM);
        configured = true;
    }

    split_x_kernel<<<MM * CC / 4 / 256, 256>>>(x);
    split_w_kernel<<<dim3(32, 32, 3), dim3(32, 32)>>>(Wq, Wk, Wv);

    qkv_gemm_tc<<<dim3(CC / 128, MM / 128, 3), 512, GEMM_SMEM>>>(bq, bk, bv);
    attn_tc<<<dim3(TT / 128, BB * HH), 256, ATT_SMEM>>>();
    out_gemm_tc<<<dim3(CC / 128, MM / 128), 512, GEMM_SMEM>>>(bv, out);
}